// round 16
// baseline (speedup 1.0000x reference)
#include <cuda_runtime.h>
#include <cuda_bf16.h>
#include <math.h>

#define SEQ 4096
#define NF 2048
#define HID 1024
#define GATES 4096
#define TAGS 10
#define START_TAG 8
#define STOP_TAG 9
#define NCTA 74        // CTAs per direction in the scan
#define NHC 14         // h-elements owned per CTA (74*14 >= 1024)
#define ROWS 56        // 4 gates * NHC weight rows per CTA
#define NJR 6          // weight col-chunks in registers (j=0..5); j=6,7 in SMEM

// packed f32x2 FMA: d = a*b + d (per 32-bit half, exact fp32)
#define FFMA2(d, a, b) asm("fma.rn.f32x2 %0, %1, %2, %3;" \
                           : "=l"(d) : "l"(a), "l"(b), "l"(d))
#define PACKF2(out, lo, hi) asm("mov.b64 %0, {%1, %2};" : "=l"(out) : "f"(lo), "f"(hi))
#define UNPACKF2(lo, hi, in) asm("mov.b64 {%0, %1}, %2;" : "=f"(lo), "=f"(hi) : "l"(in))

// fast transcendentals: MUFU-based (validated R14: rel_err unchanged)
__device__ __forceinline__ float fsig(float x) {
    return __fdividef(1.0f, 1.0f + __expf(-x));
}
__device__ __forceinline__ float ftanh(float x) {
    return 1.0f - __fdividef(2.0f, __expf(2.0f * x) + 1.0f);
}

// ---------------- scratch (module-static; no runtime allocation) ----------------
__device__ float g_xp[2][SEQ][GATES];   // precomputed input projections
__device__ float g_h[2][SEQ][HID];      // per-direction hidden states
__device__ float g_feats[SEQ][TAGS];
// 8 counter replicas per direction, one 128B line each: warp w polls replica w.
__device__ __align__(128) unsigned g_cnt[2][8][32];

__global__ void init_kernel() {
    const int i = blockIdx.x * blockDim.x + threadIdx.x;
    if (i < 2 * 8 * 32) ((unsigned*)g_cnt)[i] = 0u;
}

__global__ void dummy_kernelA() {}      // keep ncu capture slot on lstm_scan (4th launch)

// ---------------- Kernel 1: xp = X @ W_ih^T + b  (both directions) ----------------
// EXACT champion structure (single-buffer, prefetch, f32x2).
__global__ void __launch_bounds__(256, 2) gemm_xp(const float* __restrict__ X,
                                                  const float* __restrict__ Wf,
                                                  const float* __restrict__ bf,
                                                  const float* __restrict__ Wb,
                                                  const float* __restrict__ bb)
{
    const int dir = blockIdx.z;
    const float* __restrict__ Wg   = dir ? Wb : Wf;
    const float* __restrict__ bias = dir ? bb : bf;

    __shared__ __align__(16) float As[8][128];
    __shared__ __align__(16) float Bs[8][128];

    const int tid = threadIdx.x;
    const int tx = tid & 15, ty = tid >> 4;
    const int bm = blockIdx.y * 128;
    const int bn = blockIdx.x * 128;

    unsigned long long acc2[8][4];
#pragma unroll
    for (int i = 0; i < 8; i++)
#pragma unroll
        for (int j = 0; j < 4; j++) acc2[i][j] = 0ull;

    const int lr = tid >> 1;
    const int lc = (tid & 1) * 4;
    const float* Ap = X  + (size_t)(bm + lr) * NF + lc;
    const float* Bp = Wg + (size_t)(bn + lr) * NF + lc;

    float4 a = *(const float4*)Ap;
    float4 b = *(const float4*)Bp;

    for (int k0 = 0; k0 < NF; k0 += 8) {
        __syncthreads();
        As[lc + 0][lr] = a.x; As[lc + 1][lr] = a.y; As[lc + 2][lr] = a.z; As[lc + 3][lr] = a.w;
        Bs[lc + 0][lr] = b.x; Bs[lc + 1][lr] = b.y; Bs[lc + 2][lr] = b.z; Bs[lc + 3][lr] = b.w;
        __syncthreads();
        if (k0 + 8 < NF) {                       // prefetch next tile under compute
            a = *(const float4*)(Ap + k0 + 8);
            b = *(const float4*)(Bp + k0 + 8);
        }
#pragma unroll
        for (int k = 0; k < 8; k++) {
            float4 a0 = *(const float4*)&As[k][ty * 4];
            float4 a1 = *(const float4*)&As[k][64 + ty * 4];
            ulonglong2 b0 = *(const ulonglong2*)&Bs[k][tx * 4];
            ulonglong2 b1 = *(const ulonglong2*)&Bs[k][64 + tx * 4];
            float av[8] = {a0.x, a0.y, a0.z, a0.w, a1.x, a1.y, a1.z, a1.w};
#pragma unroll
            for (int i = 0; i < 8; i++) {
                unsigned long long ad;
                PACKF2(ad, av[i], av[i]);
                FFMA2(acc2[i][0], ad, b0.x);
                FFMA2(acc2[i][1], ad, b0.y);
                FFMA2(acc2[i][2], ad, b1.x);
                FFMA2(acc2[i][3], ad, b1.y);
            }
        }
    }

#pragma unroll
    for (int i = 0; i < 8; i++) {
        const int row = bm + ((i < 4) ? (ty * 4 + i) : (64 + ty * 4 + i - 4));
#pragma unroll
        for (int jp = 0; jp < 4; jp++) {
            const int col = bn + ((jp < 2) ? (tx * 4 + jp * 2) : (64 + tx * 4 + (jp - 2) * 2));
            float lo, hi;
            UNPACKF2(lo, hi, acc2[i][jp]);
            g_xp[dir][row][col + 0] = lo + bias[col + 0];
            g_xp[dir][row][col + 1] = hi + bias[col + 1];
        }
    }
}

// ---------------- Kernel 2: persistent bidirectional LSTM scan ----------------
// R14 partition/compute EXACTLY. Sync restructured: per-warp self-gating polls on
// 8 counter replicas; single producer/consumer named barrier; no __syncthreads
// in the step loop. Warps 1-7 overlap warp0's combine+release with their poll.
__global__ void __launch_bounds__(256, 1) lstm_scan(const float* __restrict__ Whf,
                                                    const float* __restrict__ Whb)
{
    extern __shared__ __align__(16) float Wsh[];  // [ROWS][256] cols 768..1023
    __shared__ float asum[64];                    // post-activation gate values

    const int dir = (blockIdx.x >= NCTA) ? 1 : 0;
    const int ci  = blockIdx.x - dir * NCTA;
    const float* __restrict__ W = dir ? Whb : Whf;
    const int hstart = ci * NHC;

    const int tid  = threadIdx.x;
    const int lane = tid & 31;
    const int warp = tid >> 5;
    const int rbase = warp * 7;
    const bool tanh_warp = (warp == 4 || warp == 5);   // rows 28..41 = gate g
    unsigned* const mycnt = &g_cnt[dir][warp][0];      // this warp's poll replica

    // ---- register-resident weight chunks (cols 0..767): 168 regs ----
    unsigned long long wreg[7][NJR][2];
#pragma unroll
    for (int rr = 0; rr < 7; rr++) {
        const int r = rbase + rr;
        const int gate = r / NHC, lh = r % NHC;
        int hg = hstart + lh; if (hg >= HID) hg = HID - 1;  // clamp; values unused
        const float* wrow = W + (size_t)(gate * HID + hg) * HID;
#pragma unroll
        for (int j = 0; j < NJR; j++) {
            float4 v = *(const float4*)&wrow[j * 128 + lane * 4];
            PACKF2(wreg[rr][j][0], v.x, v.y);
            PACKF2(wreg[rr][j][1], v.z, v.w);
        }
    }
    // ---- cooperative SMEM load of cols 768..1023 ----
    for (int idx = tid; idx < ROWS * 64; idx += 256) {
        const int r = idx >> 6, c4 = idx & 63;
        const int gate = r / NHC, lh = r % NHC;
        int hg = hstart + lh; if (hg >= HID) hg = HID - 1;
        float4 v = *(const float4*)&W[(size_t)(gate * HID + hg) * HID + 768 + c4 * 4];
        *(float4*)&Wsh[r * 256 + c4 * 4] = v;
    }

    // lane rr (<7) holds xp for row rbase+rr of the current step
    int myrow = 0;
    float xpcur = 0.f;
    if (lane < 7) {
        const int r = rbase + lane;
        const int gate = r / NHC;
        int hg = hstart + r % NHC; if (hg >= HID) hg = HID - 1;
        myrow = gate * HID + hg;
        xpcur = g_xp[dir][dir ? (SEQ - 1) : 0][myrow];
    }
    float creg = 0.f;                               // warp0 lanes 0..13: cell state
    __syncthreads();                                // one-time: Wsh ready

    for (int t = 0; t < SEQ; ++t) {
        const int time = dir ? (SEQ - 1 - t) : t;

        // prefetch next step's xp BEFORE the poll (hidden under spin)
        float xpn = 0.f;
        if (lane < 7 && t + 1 < SEQ)
            xpn = g_xp[dir][dir ? (time - 1) : (time + 1)][myrow];

        // per-warp self-gate: all lanes acquire-poll this warp's replica
        // (uniform address -> 1 coalesced request per poll; 74 pollers/line)
        if (t > 0) {
            const unsigned target = (unsigned)(NCTA * t);
            unsigned v;
            do {
                asm volatile("ld.acquire.gpu.global.u32 %0, [%1];"
                             : "=r"(v) : "l"(mycnt) : "memory");
            } while (v < target);
        }

        // load h_{prev} as packed f32x2 pairs (MLP=8) — no barrier before this
        ulonglong2 hv2[8];
        if (t > 0) {
            const int pt = dir ? (time + 1) : (time - 1);
            const ulonglong2* hp = (const ulonglong2*)&g_h[dir][pt][0];
#pragma unroll
            for (int j = 0; j < 8; j++) hv2[j] = hp[j * 32 + lane];
        } else {
#pragma unroll
            for (int j = 0; j < 8; j++) { hv2[j].x = 0ull; hv2[j].y = 0ull; }
        }

        // dot products: register chunks then SMEM chunks, f32x2 accumulation
        unsigned long long acc2[7];
#pragma unroll
        for (int rr = 0; rr < 7; rr++) acc2[rr] = 0ull;
#pragma unroll
        for (int j = 0; j < NJR; j++) {
#pragma unroll
            for (int rr = 0; rr < 7; rr++) {
                FFMA2(acc2[rr], wreg[rr][j][0], hv2[j].x);
                FFMA2(acc2[rr], wreg[rr][j][1], hv2[j].y);
            }
        }
#pragma unroll
        for (int j = NJR; j < 8; j++) {
#pragma unroll
            for (int rr = 0; rr < 7; rr++) {
                ulonglong2 w2 = *(const ulonglong2*)&Wsh[(rbase + rr) * 256 + (j - NJR) * 128 + lane * 4];
                FFMA2(acc2[rr], w2.x, hv2[j].x);
                FFMA2(acc2[rr], w2.y, hv2[j].y);
            }
        }

        // reduce; lane rr captures row rbase+rr's pre-activation
        float pre = 0.f;
#pragma unroll
        for (int rr = 0; rr < 7; rr++) {
            float lo, hi;
            UNPACKF2(lo, hi, acc2[rr]);
            float s = lo + hi;
#pragma unroll
            for (int off = 16; off; off >>= 1) s += __shfl_xor_sync(0xffffffffu, s, off);
            if (lane == rr) pre = s + xpcur;
        }

        // parallel activations: lanes 0..6 of every warp (uniform gate per warp)
        if (lane < 7) asum[rbase + lane] = tanh_warp ? ftanh(pre) : fsig(pre);
        xpcur = xpn;

        // producer/consumer named barrier: warps 1-7 arrive and go straight to
        // the next poll (overlapping warp0's tail); warp0 syncs, combines,
        // stores h, and releases all 8 replicas.
        if (warp != 0) {
            asm volatile("bar.arrive 1, 256;" ::: "memory");
            // NOTE: next-iter asum overwrite is WAR-safe: this warp can only
            // pass poll t+1 after own CTA released t (= after warp0 read asum).
        } else {
            asm volatile("bar.sync 1, 256;" ::: "memory");
            if (tid < NHC) {
                const int hg = hstart + tid;
                const float ai = asum[tid];
                const float af = asum[NHC + tid];
                const float ag = asum[2 * NHC + tid];
                const float ao = asum[3 * NHC + tid];
                const float c = af * creg + ai * ag;
                const float h = ao * ftanh(c);
                creg = c;
                if (hg < HID) g_h[dir][time][hg] = h;
            }
            __syncwarp();
            if (lane < 8) {     // one warp instruction: 8 parallel releases
                asm volatile("red.release.gpu.global.add.u32 [%0], %1;"
                             :: "l"(&g_cnt[dir][lane][0]), "r"(1u) : "memory");
            }
        }
    }
}

// ---------------- Kernel 3: feats[t] = W_lin @ concat(h_f[t], h_b[t]) + b_lin ----------------
__global__ void __launch_bounds__(320) feats_kernel(const float* __restrict__ Wl,
                                                    const float* __restrict__ bl)
{
    const int t = blockIdx.x;
    const int warp = threadIdx.x >> 5;   // = tag, exactly 10 warps
    const int lane = threadIdx.x & 31;
    const float4* hf = (const float4*)&g_h[0][t][0];
    const float4* hb = (const float4*)&g_h[1][t][0];
    const float4* w0 = (const float4*)&Wl[warp * (2 * HID)];
    const float4* w1 = (const float4*)&Wl[warp * (2 * HID) + HID];
    float s = 0.f;
#pragma unroll 4
    for (int k = lane; k < HID / 4; k += 32) {
        float4 h4 = hf[k], v4 = w0[k];
        s = fmaf(h4.x, v4.x, s); s = fmaf(h4.y, v4.y, s);
        s = fmaf(h4.z, v4.z, s); s = fmaf(h4.w, v4.w, s);
    }
#pragma unroll 4
    for (int k = lane; k < HID / 4; k += 32) {
        float4 h4 = hb[k], v4 = w1[k];
        s = fmaf(h4.x, v4.x, s); s = fmaf(h4.y, v4.y, s);
        s = fmaf(h4.z, v4.z, s); s = fmaf(h4.w, v4.w, s);
    }
#pragma unroll
    for (int off = 16; off; off >>= 1) s += __shfl_xor_sync(0xffffffffu, s, off);
    if (lane == 0) g_feats[t][warp] = s + bl[warp];
}

// ---------------- Kernel 4: Viterbi (sequential, warp-shuffle recurrence) ----------------
__global__ void __launch_bounds__(256) viterbi_kernel(const float* __restrict__ trans,
                                                      float* __restrict__ out, int out_size)
{
    extern __shared__ float sh[];
    float* sfeats = sh;                                     // SEQ*TAGS floats
    unsigned char* bps = (unsigned char*)(sh + SEQ * TAGS); // SEQ*TAGS bytes

    const int tid = threadIdx.x;
    const float* gf = &g_feats[0][0];
    for (int i = tid; i < SEQ * TAGS; i += blockDim.x) sfeats[i] = gf[i];
    __syncthreads();

    if (tid < 32) {
        const int j = tid;      // lane j holds fv[j]
        float tt[TAGS];
#pragma unroll
        for (int i = 0; i < TAGS; i++) tt[i] = (j < TAGS) ? trans[j * TAGS + i] : 0.f;

        float fv = (j == START_TAG) ? 0.f : -10000.f;
        for (int t = 0; t < SEQ; ++t) {
            float best = -3.4e38f; int arg = 0;
#pragma unroll
            for (int i = 0; i < TAGS; i++) {
                const float v = __shfl_sync(0xffffffffu, fv, i);
                const float sc = v + tt[i];
                if (sc > best) { best = sc; arg = i; }   // strict > keeps first argmax
            }
            const float feat = (j < TAGS) ? sfeats[t * TAGS + j] : 0.f;
            fv = best + feat;
            if (j < TAGS) bps[t * TAGS + j] = (unsigned char)arg;
        }

        float term = (j < TAGS) ? (fv + trans[STOP_TAG * TAGS + j]) : -3.4e38f;
        float bscore = -3.4e38f; int btag = 0;
#pragma unroll
        for (int i = 0; i < TAGS; i++) {
            const float v = __shfl_sync(0xffffffffu, term, i);
            if (v > bscore) { bscore = v; btag = i; }
        }

        if (j == 0) {
            out[0] = bscore;
            int tag = btag;
            for (int t = SEQ - 1; t >= 0; --t) {
                if (1 + t < out_size) out[1 + t] = (float)tag;
                tag = bps[t * TAGS + tag];
            }
        }
    }
}

// ---------------- launch ----------------
extern "C" void kernel_launch(void* const* d_in, const int* in_sizes, int n_in,
                              void* d_out, int out_size)
{
    const float* sentence = (const float*)d_in[0];
    const float* W_ih_f   = (const float*)d_in[1];
    const float* W_hh_f   = (const float*)d_in[2];
    const float* b_f      = (const float*)d_in[3];
    const float* W_ih_b   = (const float*)d_in[4];
    const float* W_hh_b   = (const float*)d_in[5];
    const float* b_b      = (const float*)d_in[6];
    const float* W_lin    = (const float*)d_in[7];
    const float* b_lin    = (const float*)d_in[8];
    const float* trans    = (const float*)d_in[9];

    const int scan_smem = ROWS * 256 * (int)sizeof(float);   // 57344 B
    cudaFuncSetAttribute(lstm_scan, cudaFuncAttributeMaxDynamicSharedMemorySize, scan_smem);
    cudaFuncSetAttribute(viterbi_kernel, cudaFuncAttributeMaxDynamicSharedMemorySize,
                         SEQ * TAGS * 5);                    // 204800 B

    // lstm_scan stays the 4th launch (ncu capture slot)
    dim3 gg(GATES / 128, SEQ / 128, 2);
    gemm_xp<<<gg, 256>>>(sentence, W_ih_f, b_f, W_ih_b, b_b);

    init_kernel<<<1, 512>>>();
    dummy_kernelA<<<1, 32>>>();

    lstm_scan<<<2 * NCTA, 256, scan_smem>>>(W_hh_f, W_hh_b);

    feats_kernel<<<SEQ, 320>>>(W_lin, b_lin);

    viterbi_kernel<<<1, 256, SEQ * TAGS * 5>>>(trans, (float*)d_out, out_size);
}

// round 17
// speedup vs baseline: 1.5575x; 1.5575x over previous
#include <cuda_runtime.h>
#include <cuda_bf16.h>
#include <math.h>

#define SEQ 4096
#define NF 2048
#define HID 1024
#define GATES 4096
#define TAGS 10
#define START_TAG 8
#define STOP_TAG 9
#define NCTA 74        // CTAs per direction in the scan
#define NHC 14         // h-elements owned per CTA (74*14 >= 1024)
#define ROWS 56        // 4 gates * NHC weight rows per CTA
#define NJR 6          // weight col-chunks in registers (j=0..5); j=6,7 in SMEM

// packed f32x2 FMA: d = a*b + d (per 32-bit half, exact fp32)
#define FFMA2(d, a, b) asm("fma.rn.f32x2 %0, %1, %2, %3;" \
                           : "=l"(d) : "l"(a), "l"(b), "l"(d))
#define PACKF2(out, lo, hi) asm("mov.b64 %0, {%1, %2};" : "=l"(out) : "f"(lo), "f"(hi))
#define UNPACKF2(lo, hi, in) asm("mov.b64 {%0, %1}, %2;" : "=f"(lo), "=f"(hi) : "l"(in))

// fast transcendentals: MUFU-based (validated R14: rel_err unchanged)
__device__ __forceinline__ float fsig(float x) {
    return __fdividef(1.0f, 1.0f + __expf(-x));
}
__device__ __forceinline__ float ftanh(float x) {
    return 1.0f - __fdividef(2.0f, __expf(2.0f * x) + 1.0f);
}

// ---------------- scratch (module-static; no runtime allocation) ----------------
__device__ float g_xp[2][SEQ][GATES];   // precomputed input projections
__device__ float g_h[2][SEQ][HID];      // per-direction hidden states
__device__ float g_feats[SEQ][TAGS];
__device__ __align__(256) unsigned g_cnt[128];   // [0]=dir0, [64]=dir1 (separate lines)

__global__ void init_kernel() {
    if (threadIdx.x < 128) g_cnt[threadIdx.x] = 0u;
}

__global__ void dummy_kernelA() {}      // keep ncu capture slot on lstm_scan (4th launch)

// ---------------- Kernel 1: xp = X @ W_ih^T + b  (both directions) ----------------
// Champion GEMM + double-buffered SMEM: ONE __syncthreads per k-tile; STS of
// tile i+1 overlaps compute of tile i. Accumulation order unchanged (bit-exact).
__global__ void __launch_bounds__(256, 2) gemm_xp(const float* __restrict__ X,
                                                  const float* __restrict__ Wf,
                                                  const float* __restrict__ bf,
                                                  const float* __restrict__ Wb,
                                                  const float* __restrict__ bb)
{
    const int dir = blockIdx.z;
    const float* __restrict__ Wg   = dir ? Wb : Wf;
    const float* __restrict__ bias = dir ? bb : bf;

    __shared__ __align__(16) float As[2][8][128];
    __shared__ __align__(16) float Bs[2][8][128];

    const int tid = threadIdx.x;
    const int tx = tid & 15, ty = tid >> 4;
    const int bm = blockIdx.y * 128;
    const int bn = blockIdx.x * 128;

    unsigned long long acc2[8][4];
#pragma unroll
    for (int i = 0; i < 8; i++)
#pragma unroll
        for (int j = 0; j < 4; j++) acc2[i][j] = 0ull;

    const int lr = tid >> 1;
    const int lc = (tid & 1) * 4;
    const float* Ap = X  + (size_t)(bm + lr) * NF + lc;
    const float* Bp = Wg + (size_t)(bn + lr) * NF + lc;

    // prologue: tile 0 into buffer 0
    {
        float4 a = *(const float4*)Ap;
        float4 b = *(const float4*)Bp;
        As[0][lc + 0][lr] = a.x; As[0][lc + 1][lr] = a.y;
        As[0][lc + 2][lr] = a.z; As[0][lc + 3][lr] = a.w;
        Bs[0][lc + 0][lr] = b.x; Bs[0][lc + 1][lr] = b.y;
        Bs[0][lc + 2][lr] = b.z; Bs[0][lc + 3][lr] = b.w;
    }
    __syncthreads();

    int cur = 0;
    for (int k0 = 0; k0 < NF; k0 += 8) {
        float4 a, b;
        const bool has_next = (k0 + 8 < NF);
        if (has_next) {                          // LDG issued, hidden under compute
            a = *(const float4*)(Ap + k0 + 8);
            b = *(const float4*)(Bp + k0 + 8);
        }
#pragma unroll
        for (int k = 0; k < 8; k++) {
            float4 a0 = *(const float4*)&As[cur][k][ty * 4];
            float4 a1 = *(const float4*)&As[cur][k][64 + ty * 4];
            ulonglong2 b0 = *(const ulonglong2*)&Bs[cur][k][tx * 4];
            ulonglong2 b1 = *(const ulonglong2*)&Bs[cur][k][64 + tx * 4];
            float av[8] = {a0.x, a0.y, a0.z, a0.w, a1.x, a1.y, a1.z, a1.w};
#pragma unroll
            for (int i = 0; i < 8; i++) {
                unsigned long long ad;
                PACKF2(ad, av[i], av[i]);
                FFMA2(acc2[i][0], ad, b0.x);
                FFMA2(acc2[i][1], ad, b0.y);
                FFMA2(acc2[i][2], ad, b1.x);
                FFMA2(acc2[i][3], ad, b1.y);
            }
        }
        if (has_next) {
            const int nxt = cur ^ 1;
            As[nxt][lc + 0][lr] = a.x; As[nxt][lc + 1][lr] = a.y;
            As[nxt][lc + 2][lr] = a.z; As[nxt][lc + 3][lr] = a.w;
            Bs[nxt][lc + 0][lr] = b.x; Bs[nxt][lc + 1][lr] = b.y;
            Bs[nxt][lc + 2][lr] = b.z; Bs[nxt][lc + 3][lr] = b.w;
            __syncthreads();                     // single barrier per tile
            cur = nxt;
        }
    }

#pragma unroll
    for (int i = 0; i < 8; i++) {
        const int row = bm + ((i < 4) ? (ty * 4 + i) : (64 + ty * 4 + i - 4));
#pragma unroll
        for (int jp = 0; jp < 4; jp++) {
            const int col = bn + ((jp < 2) ? (tx * 4 + jp * 2) : (64 + tx * 4 + (jp - 2) * 2));
            float lo, hi;
            UNPACKF2(lo, hi, acc2[i][jp]);
            g_xp[dir][row][col + 0] = lo + bias[col + 0];
            g_xp[dir][row][col + 1] = hi + bias[col + 1];
        }
    }
}

// ---------------- Kernel 2: persistent bidirectional LSTM scan ----------------
// EXACT R14 champion (11.77ms): fast transcendentals, parallel activations,
// warp-local tail, relaxed poll + single acquire, lane-held xp. Unchanged.
__global__ void __launch_bounds__(256, 1) lstm_scan(const float* __restrict__ Whf,
                                                    const float* __restrict__ Whb)
{
    extern __shared__ __align__(16) float Wsh[];  // [ROWS][256] cols 768..1023
    __shared__ float asum[64];                    // post-activation gate values

    const int dir = (blockIdx.x >= NCTA) ? 1 : 0;
    const int ci  = blockIdx.x - dir * NCTA;
    const float* __restrict__ W = dir ? Whb : Whf;
    unsigned* const cnt = &g_cnt[dir * 64];
    const int hstart = ci * NHC;

    const int tid  = threadIdx.x;
    const int lane = tid & 31;
    const int warp = tid >> 5;
    const int rbase = warp * 7;
    const bool tanh_warp = (warp == 4 || warp == 5);   // rows 28..41 = gate g

    // ---- register-resident weight chunks (cols 0..767): 168 regs ----
    unsigned long long wreg[7][NJR][2];
#pragma unroll
    for (int rr = 0; rr < 7; rr++) {
        const int r = rbase + rr;
        const int gate = r / NHC, lh = r % NHC;
        int hg = hstart + lh; if (hg >= HID) hg = HID - 1;  // clamp; values unused
        const float* wrow = W + (size_t)(gate * HID + hg) * HID;
#pragma unroll
        for (int j = 0; j < NJR; j++) {
            float4 v = *(const float4*)&wrow[j * 128 + lane * 4];
            PACKF2(wreg[rr][j][0], v.x, v.y);
            PACKF2(wreg[rr][j][1], v.z, v.w);
        }
    }
    // ---- cooperative SMEM load of cols 768..1023 ----
    for (int idx = tid; idx < ROWS * 64; idx += 256) {
        const int r = idx >> 6, c4 = idx & 63;
        const int gate = r / NHC, lh = r % NHC;
        int hg = hstart + lh; if (hg >= HID) hg = HID - 1;
        float4 v = *(const float4*)&W[(size_t)(gate * HID + hg) * HID + 768 + c4 * 4];
        *(float4*)&Wsh[r * 256 + c4 * 4] = v;
    }

    // lane rr (<7) holds xp for row rbase+rr of the current step
    int myrow = 0;
    float xpcur = 0.f;
    if (lane < 7) {
        const int r = rbase + lane;
        const int gate = r / NHC;
        int hg = hstart + r % NHC; if (hg >= HID) hg = HID - 1;
        myrow = gate * HID + hg;
        xpcur = g_xp[dir][dir ? (SEQ - 1) : 0][myrow];
    }
    float creg = 0.f;
    __syncthreads();

    for (int t = 0; t < SEQ; ++t) {
        const int time = dir ? (SEQ - 1 - t) : t;

        // prefetch next step's xp BEFORE the poll (latency fully hidden)
        float xpn = 0.f;
        if (lane < 7 && t + 1 < SEQ)
            xpn = g_xp[dir][dir ? (time - 1) : (time + 1)][myrow];

        // grid sync: tid0 relaxed-polls, ONE acquire on detect, block barrier
        if (t > 0) {
            if (tid == 0) {
                const unsigned target = (unsigned)(NCTA * t);
                unsigned v;
                do {
                    asm volatile("ld.relaxed.gpu.global.u32 %0, [%1];"
                                 : "=r"(v) : "l"(cnt) : "memory");
                } while (v < target);
                asm volatile("ld.acquire.gpu.global.u32 %0, [%1];"
                             : "=r"(v) : "l"(cnt) : "memory");
            }
            __syncthreads();
        }

        // load h_{prev} as packed f32x2 pairs (MLP=8)
        ulonglong2 hv2[8];
        if (t > 0) {
            const int pt = dir ? (time + 1) : (time - 1);
            const ulonglong2* hp = (const ulonglong2*)&g_h[dir][pt][0];
#pragma unroll
            for (int j = 0; j < 8; j++) hv2[j] = hp[j * 32 + lane];
        } else {
#pragma unroll
            for (int j = 0; j < 8; j++) { hv2[j].x = 0ull; hv2[j].y = 0ull; }
        }

        // dot products: register chunks then SMEM chunks, f32x2 accumulation
        unsigned long long acc2[7];
#pragma unroll
        for (int rr = 0; rr < 7; rr++) acc2[rr] = 0ull;
#pragma unroll
        for (int j = 0; j < NJR; j++) {
#pragma unroll
            for (int rr = 0; rr < 7; rr++) {
                FFMA2(acc2[rr], wreg[rr][j][0], hv2[j].x);
                FFMA2(acc2[rr], wreg[rr][j][1], hv2[j].y);
            }
        }
#pragma unroll
        for (int j = NJR; j < 8; j++) {
#pragma unroll
            for (int rr = 0; rr < 7; rr++) {
                ulonglong2 w2 = *(const ulonglong2*)&Wsh[(rbase + rr) * 256 + (j - NJR) * 128 + lane * 4];
                FFMA2(acc2[rr], w2.x, hv2[j].x);
                FFMA2(acc2[rr], w2.y, hv2[j].y);
            }
        }

        // reduce; lane rr captures row rbase+rr's pre-activation
        float pre = 0.f;
#pragma unroll
        for (int rr = 0; rr < 7; rr++) {
            float lo, hi;
            UNPACKF2(lo, hi, acc2[rr]);
            float s = lo + hi;
#pragma unroll
            for (int off = 16; off; off >>= 1) s += __shfl_xor_sync(0xffffffffu, s, off);
            if (lane == rr) pre = s + xpcur;
        }

        // parallel activations: lanes 0..6 of EVERY warp (uniform gate per warp)
        if (lane < 7) asum[rbase + lane] = tanh_warp ? ftanh(pre) : fsig(pre);
        xpcur = xpn;
        __syncthreads();        // asum published

        // warp 0 only: cheap combine, h store, release (no CTA-wide tail barrier)
        if (warp == 0) {
            if (tid < NHC) {
                const int hg = hstart + tid;
                const float ai = asum[tid];
                const float af = asum[NHC + tid];
                const float ag = asum[2 * NHC + tid];
                const float ao = asum[3 * NHC + tid];
                const float c = af * creg + ai * ag;
                const float h = ao * ftanh(c);
                creg = c;
                if (hg < HID) g_h[dir][time][hg] = h;
            }
            __syncwarp();
            if (lane == 0) {
                unsigned one = 1u;
                asm volatile("red.release.gpu.global.add.u32 [%0], %1;"
                             :: "l"(cnt), "r"(one) : "memory");
            }
        }
    }
}

// ---------------- Kernel 3: feats[t] = W_lin @ concat(h_f[t], h_b[t]) + b_lin ----------------
__global__ void __launch_bounds__(320) feats_kernel(const float* __restrict__ Wl,
                                                    const float* __restrict__ bl)
{
    const int t = blockIdx.x;
    const int warp = threadIdx.x >> 5;   // = tag, exactly 10 warps
    const int lane = threadIdx.x & 31;
    const float4* hf = (const float4*)&g_h[0][t][0];
    const float4* hb = (const float4*)&g_h[1][t][0];
    const float4* w0 = (const float4*)&Wl[warp * (2 * HID)];
    const float4* w1 = (const float4*)&Wl[warp * (2 * HID) + HID];
    float s = 0.f;
#pragma unroll 4
    for (int k = lane; k < HID / 4; k += 32) {
        float4 h4 = hf[k], v4 = w0[k];
        s = fmaf(h4.x, v4.x, s); s = fmaf(h4.y, v4.y, s);
        s = fmaf(h4.z, v4.z, s); s = fmaf(h4.w, v4.w, s);
    }
#pragma unroll 4
    for (int k = lane; k < HID / 4; k += 32) {
        float4 h4 = hb[k], v4 = w1[k];
        s = fmaf(h4.x, v4.x, s); s = fmaf(h4.y, v4.y, s);
        s = fmaf(h4.z, v4.z, s); s = fmaf(h4.w, v4.w, s);
    }
#pragma unroll
    for (int off = 16; off; off >>= 1) s += __shfl_xor_sync(0xffffffffu, s, off);
    if (lane == 0) g_feats[t][warp] = s + bl[warp];
}

// ---------------- Kernel 4: Viterbi (sequential, warp-shuffle recurrence) ----------------
__global__ void __launch_bounds__(256) viterbi_kernel(const float* __restrict__ trans,
                                                      float* __restrict__ out, int out_size)
{
    extern __shared__ float sh[];
    float* sfeats = sh;                                     // SEQ*TAGS floats
    unsigned char* bps = (unsigned char*)(sh + SEQ * TAGS); // SEQ*TAGS bytes

    const int tid = threadIdx.x;
    const float* gf = &g_feats[0][0];
    for (int i = tid; i < SEQ * TAGS; i += blockDim.x) sfeats[i] = gf[i];
    __syncthreads();

    if (tid < 32) {
        const int j = tid;      // lane j holds fv[j]
        float tt[TAGS];
#pragma unroll
        for (int i = 0; i < TAGS; i++) tt[i] = (j < TAGS) ? trans[j * TAGS + i] : 0.f;

        float fv = (j == START_TAG) ? 0.f : -10000.f;
        for (int t = 0; t < SEQ; ++t) {
            float best = -3.4e38f; int arg = 0;
#pragma unroll
            for (int i = 0; i < TAGS; i++) {
                const float v = __shfl_sync(0xffffffffu, fv, i);
                const float sc = v + tt[i];
                if (sc > best) { best = sc; arg = i; }   // strict > keeps first argmax
            }
            const float feat = (j < TAGS) ? sfeats[t * TAGS + j] : 0.f;
            fv = best + feat;
            if (j < TAGS) bps[t * TAGS + j] = (unsigned char)arg;
        }

        float term = (j < TAGS) ? (fv + trans[STOP_TAG * TAGS + j]) : -3.4e38f;
        float bscore = -3.4e38f; int btag = 0;
#pragma unroll
        for (int i = 0; i < TAGS; i++) {
            const float v = __shfl_sync(0xffffffffu, term, i);
            if (v > bscore) { bscore = v; btag = i; }
        }

        if (j == 0) {
            out[0] = bscore;
            int tag = btag;
            for (int t = SEQ - 1; t >= 0; --t) {
                if (1 + t < out_size) out[1 + t] = (float)tag;
                tag = bps[t * TAGS + tag];
            }
        }
    }
}

// ---------------- launch ----------------
extern "C" void kernel_launch(void* const* d_in, const int* in_sizes, int n_in,
                              void* d_out, int out_size)
{
    const float* sentence = (const float*)d_in[0];
    const float* W_ih_f   = (const float*)d_in[1];
    const float* W_hh_f   = (const float*)d_in[2];
    const float* b_f      = (const float*)d_in[3];
    const float* W_ih_b   = (const float*)d_in[4];
    const float* W_hh_b   = (const float*)d_in[5];
    const float* b_b      = (const float*)d_in[6];
    const float* W_lin    = (const float*)d_in[7];
    const float* b_lin    = (const float*)d_in[8];
    const float* trans    = (const float*)d_in[9];

    const int scan_smem = ROWS * 256 * (int)sizeof(float);   // 57344 B
    cudaFuncSetAttribute(lstm_scan, cudaFuncAttributeMaxDynamicSharedMemorySize, scan_smem);
    cudaFuncSetAttribute(viterbi_kernel, cudaFuncAttributeMaxDynamicSharedMemorySize,
                         SEQ * TAGS * 5);                    // 204800 B

    // lstm_scan stays the 4th launch (ncu capture slot)
    dim3 gg(GATES / 128, SEQ / 128, 2);
    gemm_xp<<<gg, 256>>>(sentence, W_ih_f, b_f, W_ih_b, b_b);

    init_kernel<<<1, 128>>>();
    dummy_kernelA<<<1, 32>>>();

    lstm_scan<<<2 * NCTA, 256, scan_smem>>>(W_hh_f, W_hh_b);

    feats_kernel<<<SEQ, 320>>>(W_lin, b_lin);

    viterbi_kernel<<<1, 256, SEQ * TAGS * 5>>>(trans, (float*)d_out, out_size);
}